// round 10
// baseline (speedup 1.0000x reference)
#include <cuda_runtime.h>
#include <cuda_bf16.h>

#define VSA_N   2048
#define VSA_BLK 256            // 8 warps
#define VSA_ROWS_PER_BLK 16    // 2 rows per warp

// ---------------------------------------------------------------------------
// Single fused kernel. grid = (N/16, B) = (128, 4), 256 threads (8 warps),
// TWO output rows per warp: one LDS.128 of the k' tile feeds the math for
// both rows (R8 ncu showed L1/LDS crossbar at 54.9% = top pipe; halving the
// tile traffic is the targeted fix). Two rows per warp also gives two
// independent MUFU chains per lane -> better latency hiding.
//
// Phase A: block-redundant means of q,k,v for the batch (L2-resident).
// Phase B: stage k' = (k - mk) * c1 as float4 (xyz, |k'|^2), c1=log2e/sqrt(N).
// Phase C: hot loop. ALGEBRA: T_i = q_i x (sum_j e_ij k_j) (bilinear) and
//          |q x k|^2 = |q|^2|k|^2 - (q.k)^2 (Lagrange). Per pair-row:
//          3 FMA dot + 2 FMA n2 + FMNMX + MUFU sqrt + MUFU ex2 + 4 accum FMA,
//          + 0.5 LDS.128 (shared between the 2 rows).
// Phase D: warp reduce both rows' (Z,W); lanes 0/1 run the two epilogues.
// ---------------------------------------------------------------------------
__global__ __launch_bounds__(VSA_BLK, 6)
void vsa_fused_kernel(const float* __restrict__ q,
                      const float* __restrict__ k,
                      const float* __restrict__ v,
                      float* __restrict__ out) {
    __shared__ float4 sk[VSA_N];          // 32 KB
    __shared__ float  red[VSA_BLK / 32][9];
    __shared__ float  means[9];

    const int tid  = threadIdx.x;
    const int b    = blockIdx.y;
    const int warp = tid >> 5;
    const int lane = tid & 31;

    const float* qb = q + (size_t)b * VSA_N * 3;
    const float* kb = k + (size_t)b * VSA_N * 3;
    const float* vb = v + (size_t)b * VSA_N * 3;

    // ---- Phase A: per-batch means (block-redundant) ----
    {
        float s[9];
#pragma unroll
        for (int c = 0; c < 9; c++) s[c] = 0.0f;

#pragma unroll
        for (int r = 0; r < VSA_N / VSA_BLK; r++) {
            const int o = (tid + r * VSA_BLK) * 3;
            s[0] += qb[o + 0]; s[1] += qb[o + 1]; s[2] += qb[o + 2];
            s[3] += kb[o + 0]; s[4] += kb[o + 1]; s[5] += kb[o + 2];
            s[6] += vb[o + 0]; s[7] += vb[o + 1]; s[8] += vb[o + 2];
        }
#pragma unroll
        for (int c = 0; c < 9; c++) {
#pragma unroll
            for (int off = 16; off > 0; off >>= 1)
                s[c] += __shfl_xor_sync(0xFFFFFFFFu, s[c], off);
        }
        if (lane == 0) {
#pragma unroll
            for (int c = 0; c < 9; c++) red[warp][c] = s[c];
        }
        __syncthreads();
        if (tid < 9) {
            float t = 0.0f;
#pragma unroll
            for (int w = 0; w < VSA_BLK / 32; w++) t += red[w][tid];
            means[tid] = t * (1.0f / (float)VSA_N);
        }
        __syncthreads();
    }

    const float mqx = means[0], mqy = means[1], mqz = means[2];
    const float mkx = means[3], mky = means[4], mkz = means[5];
    const float mvx = means[6], mvy = means[7], mvz = means[8];

    // c1 = log2(e) / sqrt(2048)
    const float c1 = 1.4426950408889634f * 0.022097086912079612f;

    // ---- Phase B: stage k' (re-read k; L2-hot from phase A) ----
#pragma unroll
    for (int r = 0; r < VSA_N / VSA_BLK; r++) {
        const int j = tid + r * VSA_BLK;
        const float kx = (kb[j * 3 + 0] - mkx) * c1;
        const float ky = (kb[j * 3 + 1] - mky) * c1;
        const float kz = (kb[j * 3 + 2] - mkz) * c1;
        const float kk = fmaf(kx, kx, fmaf(ky, ky, kz * kz));
        sk[j] = make_float4(kx, ky, kz, kk);
    }
    __syncthreads();

    // ---- Phase C: hot loop, 2 rows per warp ----
    const int i0 = blockIdx.x * VSA_ROWS_PER_BLK + warp * 2;
    const int i1 = i0 + 1;

    const float qx0 = qb[i0 * 3 + 0] - mqx;
    const float qy0 = qb[i0 * 3 + 1] - mqy;
    const float qz0 = qb[i0 * 3 + 2] - mqz;
    const float qq0 = fmaf(qx0, qx0, fmaf(qy0, qy0, qz0 * qz0));

    const float qx1 = qb[i1 * 3 + 0] - mqx;
    const float qy1 = qb[i1 * 3 + 1] - mqy;
    const float qz1 = qb[i1 * 3 + 2] - mqz;
    const float qq1 = fmaf(qx1, qx1, fmaf(qy1, qy1, qz1 * qz1));

    float Z0 = 0.0f, Wx0 = 0.0f, Wy0 = 0.0f, Wz0 = 0.0f;
    float Z1 = 0.0f, Wx1 = 0.0f, Wy1 = 0.0f, Wz1 = 0.0f;

#pragma unroll 4
    for (int s = 0; s < VSA_N / 32; s++) {
        const float4 f = sk[s * 32 + lane];

        const float dot0 = fmaf(qx0, f.x, fmaf(qy0, f.y, qz0 * f.z));
        const float dot1 = fmaf(qx1, f.x, fmaf(qy1, f.y, qz1 * f.z));

        float n20 = fmaf(-dot0, dot0, qq0 * f.w);
        float n21 = fmaf(-dot1, dot1, qq1 * f.w);
        n20 = fmaxf(n20, 0.0f);
        n21 = fmaxf(n21, 0.0f);

        float e0, e1;
        asm("sqrt.approx.f32 %0, %1;" : "=f"(e0) : "f"(n20));
        asm("sqrt.approx.f32 %0, %1;" : "=f"(e1) : "f"(n21));
        asm("ex2.approx.f32 %0, %1;"  : "=f"(e0) : "f"(e0));
        asm("ex2.approx.f32 %0, %1;"  : "=f"(e1) : "f"(e1));

        Z0 += e0;                    Z1 += e1;
        Wx0 = fmaf(e0, f.x, Wx0);    Wx1 = fmaf(e1, f.x, Wx1);
        Wy0 = fmaf(e0, f.y, Wy0);    Wy1 = fmaf(e1, f.y, Wy1);
        Wz0 = fmaf(e0, f.z, Wz0);    Wz1 = fmaf(e1, f.z, Wz1);
    }

    // ---- Phase D: warp reduce both rows, two-lane epilogue ----
#pragma unroll
    for (int off = 16; off > 0; off >>= 1) {
        Z0  += __shfl_xor_sync(0xFFFFFFFFu, Z0,  off);
        Wx0 += __shfl_xor_sync(0xFFFFFFFFu, Wx0, off);
        Wy0 += __shfl_xor_sync(0xFFFFFFFFu, Wy0, off);
        Wz0 += __shfl_xor_sync(0xFFFFFFFFu, Wz0, off);
        Z1  += __shfl_xor_sync(0xFFFFFFFFu, Z1,  off);
        Wx1 += __shfl_xor_sync(0xFFFFFFFFu, Wx1, off);
        Wy1 += __shfl_xor_sync(0xFFFFFFFFu, Wy1, off);
        Wz1 += __shfl_xor_sync(0xFFFFFFFFu, Wz1, off);
    }

    if (lane < 2) {
        // lane 0 -> row i0, lane 1 -> row i1 (all lanes hold both sums)
        const int   i  = (lane == 0) ? i0 : i1;
        const float Z  = (lane == 0) ? Z0  : Z1;
        const float Wx = (lane == 0) ? Wx0 : Wx1;
        const float Wy = (lane == 0) ? Wy0 : Wy1;
        const float Wz = (lane == 0) ? Wz0 : Wz1;
        const float qx = (lane == 0) ? qx0 : qx1;
        const float qy = (lane == 0) ? qy0 : qy1;
        const float qz = (lane == 0) ? qz0 : qz1;

        // T' = q x W (= c1 * T);  u = cross(T, v_c) / (Z * N)
        const float Tx = fmaf(qy, Wz, -qz * Wy);
        const float Ty = fmaf(qz, Wx, -qx * Wz);
        const float Tz = fmaf(qx, Wy, -qy * Wx);
        const float vx = vb[i * 3 + 0] - mvx;
        const float vy = vb[i * 3 + 1] - mvy;
        const float vz = vb[i * 3 + 2] - mvz;
        const float inv = 1.0f / (Z * (float)VSA_N * c1);
        float* o = out + ((size_t)b * VSA_N + i) * 3;
        o[0] = fmaf(Ty, vz, -Tz * vy) * inv;
        o[1] = fmaf(Tz, vx, -Tx * vz) * inv;
        o[2] = fmaf(Tx, vy, -Ty * vx) * inv;
    }
}

// ---------------------------------------------------------------------------
extern "C" void kernel_launch(void* const* d_in, const int* in_sizes, int n_in,
                              void* d_out, int out_size) {
    const float* q = (const float*)d_in[0];
    const float* k = (const float*)d_in[1];
    const float* v = (const float*)d_in[2];
    float* out = (float*)d_out;

    const int B = out_size / (VSA_N * 3);   // = 4

    dim3 grid(VSA_N / VSA_ROWS_PER_BLK, B); // (128, 4) = 512 blocks
    vsa_fused_kernel<<<grid, VSA_BLK>>>(q, k, v, out);
}

// round 11
// speedup vs baseline: 1.0183x; 1.0183x over previous
#include <cuda_runtime.h>
#include <cuda_bf16.h>

#define VSA_N    2048
#define VSA_BLK  1024          // 32 warps
#define VSA_ROWS 32            // rows per block == lanes; lane owns a row
#define VSA_JSEG (VSA_N / 32)  // 64 j's per warp

// ---------------------------------------------------------------------------
// Fused kernel, TRANSPOSED decomposition. grid = (2048/32, B) = (64, 4),
// 1024 threads (32 warps).
//
//   * lane l owns output row i = bx*32 + l  (private Z,W accumulators,
//     NO per-pair shuffles)
//   * warp w covers j in [w*64, (w+1)*64)
//   * every lane of a warp reads the SAME sk[j]  -> LDS BROADCAST (N=1):
//     1 shared wavefront per 32 pairs vs 4 in the row-per-warp layout.
//     (R8 showed L1 = 54.9% -> LDS-wavefront pressure was the top pipe.)
//
// Phase A: block-redundant means of q,k,v (L2-resident).
// Phase B: stage k' = (k-mk)*c1 as float4 (xyz, |k'|^2), c1 = log2e/sqrt(N).
// Phase C: hot loop (broadcast).  ALGEBRA: T_i = q_i x (sum_j e_ij k_j),
//          |q x k|^2 = |q|^2|k|^2 - (q.k)^2, e = ex2(sqrt(n2')) raw MUFUs.
// Phase D: partials -> smem (REUSING the sk buffer after a sync; keeps
//          static smem < 48 KB), warp r reduces row r via shuffles, lane 0
//          runs the epilogue.
// ---------------------------------------------------------------------------
__global__ __launch_bounds__(VSA_BLK, 2)
void vsa_fused_kernel(const float* __restrict__ q,
                      const float* __restrict__ k,
                      const float* __restrict__ v,
                      float* __restrict__ out) {
    __shared__ float4 sk[VSA_N];           // 32 KB; reused for partials later
    __shared__ float  red[VSA_BLK / 32][9];
    __shared__ float  means[9];

    const int tid  = threadIdx.x;
    const int b    = blockIdx.y;
    const int warp = tid >> 5;
    const int lane = tid & 31;

    const float* qb = q + (size_t)b * VSA_N * 3;
    const float* kb = k + (size_t)b * VSA_N * 3;
    const float* vb = v + (size_t)b * VSA_N * 3;

    // ---- Phase A: per-batch means (block-redundant) ----
    {
        float s[9];
#pragma unroll
        for (int c = 0; c < 9; c++) s[c] = 0.0f;

#pragma unroll
        for (int r = 0; r < VSA_N / VSA_BLK; r++) {
            const int o = (tid + r * VSA_BLK) * 3;
            s[0] += qb[o + 0]; s[1] += qb[o + 1]; s[2] += qb[o + 2];
            s[3] += kb[o + 0]; s[4] += kb[o + 1]; s[5] += kb[o + 2];
            s[6] += vb[o + 0]; s[7] += vb[o + 1]; s[8] += vb[o + 2];
        }
#pragma unroll
        for (int c = 0; c < 9; c++) {
#pragma unroll
            for (int off = 16; off > 0; off >>= 1)
                s[c] += __shfl_xor_sync(0xFFFFFFFFu, s[c], off);
        }
        if (lane == 0) {
#pragma unroll
            for (int c = 0; c < 9; c++) red[warp][c] = s[c];
        }
        __syncthreads();
        if (tid < 9) {
            float t = 0.0f;
#pragma unroll
            for (int w = 0; w < VSA_BLK / 32; w++) t += red[w][tid];
            means[tid] = t * (1.0f / (float)VSA_N);
        }
        __syncthreads();
    }

    const float mqx = means[0], mqy = means[1], mqz = means[2];
    const float mkx = means[3], mky = means[4], mkz = means[5];
    const float mvx = means[6], mvy = means[7], mvz = means[8];

    // c1 = log2(e) / sqrt(2048)
    const float c1 = 1.4426950408889634f * 0.022097086912079612f;

    // ---- Phase B: stage k' (re-read k; L2-hot from phase A) ----
#pragma unroll
    for (int r = 0; r < VSA_N / VSA_BLK; r++) {
        const int j = tid + r * VSA_BLK;
        const float kx = (kb[j * 3 + 0] - mkx) * c1;
        const float ky = (kb[j * 3 + 1] - mky) * c1;
        const float kz = (kb[j * 3 + 2] - mkz) * c1;
        const float kk = fmaf(kx, kx, fmaf(ky, ky, kz * kz));
        sk[j] = make_float4(kx, ky, kz, kk);
    }
    __syncthreads();

    // ---- Phase C: hot loop. Lane l -> row i; warp w -> j segment. ----
    const int i = blockIdx.x * VSA_ROWS + lane;

    const float qx = qb[i * 3 + 0] - mqx;
    const float qy = qb[i * 3 + 1] - mqy;
    const float qz = qb[i * 3 + 2] - mqz;
    const float qq = fmaf(qx, qx, fmaf(qy, qy, qz * qz));

    float Z = 0.0f, Wx = 0.0f, Wy = 0.0f, Wz = 0.0f;

    const float4* pj = sk + warp * VSA_JSEG;
#pragma unroll 8
    for (int jj = 0; jj < VSA_JSEG; jj++) {
        const float4 f = pj[jj];            // broadcast: all lanes same addr
        const float dot = fmaf(qx, f.x, fmaf(qy, f.y, qz * f.z));
        float n2 = fmaf(-dot, dot, qq * f.w);
        n2 = fmaxf(n2, 0.0f);               // cancellation can go slightly <0
        float e;
        asm("sqrt.approx.f32 %0, %1;" : "=f"(e) : "f"(n2));
        asm("ex2.approx.f32 %0, %1;"  : "=f"(e) : "f"(e));
        Z += e;
        Wx = fmaf(e, f.x, Wx);
        Wy = fmaf(e, f.y, Wy);
        Wz = fmaf(e, f.z, Wz);
    }

    // ---- Phase D: cross-warp reduction of per-lane partials ----
    // Reuse sk as float4 part[warp*33 + lane] (padded: 33 -> 4-way max
    // conflict instead of 32-way). 32*33 = 1056 float4 <= 2048 available.
    __syncthreads();  // all warps done READING sk before we overwrite it
    float4* part = sk;
    part[warp * 33 + lane] = make_float4(Z, Wx, Wy, Wz);
    __syncthreads();

    // Warp r reduces row r: lane l holds warp-l's partial for row r.
    {
        const float4 p = part[lane * 33 + warp];
        float Zr = p.x, Wxr = p.y, Wyr = p.z, Wzr = p.w;
#pragma unroll
        for (int off = 16; off > 0; off >>= 1) {
            Zr  += __shfl_xor_sync(0xFFFFFFFFu, Zr,  off);
            Wxr += __shfl_xor_sync(0xFFFFFFFFu, Wxr, off);
            Wyr += __shfl_xor_sync(0xFFFFFFFFu, Wyr, off);
            Wzr += __shfl_xor_sync(0xFFFFFFFFu, Wzr, off);
        }

        if (lane == 0) {
            const int ir = blockIdx.x * VSA_ROWS + warp;
            const float qxr = qb[ir * 3 + 0] - mqx;
            const float qyr = qb[ir * 3 + 1] - mqy;
            const float qzr = qb[ir * 3 + 2] - mqz;
            // T' = q x W (= c1 * T);  u = cross(T, v_c) / (Z * N)
            const float Tx = fmaf(qyr, Wzr, -qzr * Wyr);
            const float Ty = fmaf(qzr, Wxr, -qxr * Wzr);
            const float Tz = fmaf(qxr, Wyr, -qyr * Wxr);
            const float vx = vb[ir * 3 + 0] - mvx;
            const float vy = vb[ir * 3 + 1] - mvy;
            const float vz = vb[ir * 3 + 2] - mvz;
            const float inv = 1.0f / (Zr * (float)VSA_N * c1);
            float* o = out + ((size_t)b * VSA_N + ir) * 3;
            o[0] = fmaf(Ty, vz, -Tz * vy) * inv;
            o[1] = fmaf(Tz, vx, -Tx * vz) * inv;
            o[2] = fmaf(Tx, vy, -Ty * vx) * inv;
        }
    }
}

// ---------------------------------------------------------------------------
extern "C" void kernel_launch(void* const* d_in, const int* in_sizes, int n_in,
                              void* d_out, int out_size) {
    const float* q = (const float*)d_in[0];
    const float* k = (const float*)d_in[1];
    const float* v = (const float*)d_in[2];
    float* out = (float*)d_out;

    const int B = out_size / (VSA_N * 3);   // = 4

    dim3 grid(VSA_N / VSA_ROWS, B);         // (64, 4) = 256 blocks
    vsa_fused_kernel<<<grid, VSA_BLK>>>(q, k, v, out);
}